// round 8
// baseline (speedup 1.0000x reference)
#include <cuda_runtime.h>
#include <math.h>

// SLAYFeatures split design:
//  Kernel A: poly[b,h,p] and prf[b,r,h,m] (quadrature-weighted) -> scratch (40 MB)
//  Kernel B: out[b, r*8192 + h*512 + p*32 + m] = poly * prf  (pure store stream)

#define NB 8
#define THREADS 256

__device__ float g_poly[8192 * 256];    // 8 MB  [b][h*16+p]
__device__ float g_prf [8192 * 1024];   // 32 MB [b][r*512 + h*32 + m]

__global__ __launch_bounds__(THREADS, 3) void slay_producer(
    const float* __restrict__ x,        // [8192,1024]
    const float* __restrict__ omega,    // [2,16,64,32]
    const float* __restrict__ anchors,  // [16,64]
    float s0, float s1, float c0, float c1, float e0, float e1)
{
    __shared__ __align__(16) float xs[NB][1024];   // normalized x rows (32 KB)

    const int t  = threadIdx.x;
    const int b0 = blockIdx.x * NB;

    // Phase 1: load + per-head normalize (16 consecutive lanes share a head)
    {
        float4 v[NB];
        float  ss[NB];
        const float4* x4 = (const float4*)x;
#pragma unroll
        for (int k = 0; k < NB; k++) {
            v[k] = x4[(size_t)(b0 + k) * 256 + t];
            ss[k] = v[k].x*v[k].x + v[k].y*v[k].y + v[k].z*v[k].z + v[k].w*v[k].w;
        }
#pragma unroll
        for (int k = 0; k < NB; k++) {
#pragma unroll
            for (int off = 8; off; off >>= 1)
                ss[k] += __shfl_xor_sync(0xffffffffu, ss[k], off);
            float inv = 1.0f / (sqrtf(fmaxf(ss[k], 1e-12f)) + 1e-4f);
            float4 w = v[k];
            w.x *= inv; w.y *= inv; w.z *= inv; w.w *= inv;
            ((float4*)xs[k])[t] = w;
        }
    }
    __syncthreads();

    // Phase 2: poly -> g_poly. thread = (h, p)
    {
        const int h = t >> 4, p = t & 15;
        float acc[NB];
#pragma unroll
        for (int k = 0; k < NB; k++) acc[k] = 0.0f;
        const float4* an = (const float4*)(anchors + p * 64);
#pragma unroll 4
        for (int d4 = 0; d4 < 16; d4++) {
            float4 a = an[d4];
#pragma unroll
            for (int k = 0; k < NB; k++) {
                float4 xv = ((const float4*)xs[k])[h * 16 + d4];
                acc[k] += xv.x*a.x + xv.y*a.y + xv.z*a.z + xv.w*a.w;
            }
        }
#pragma unroll
        for (int k = 0; k < NB; k++)
            g_poly[(size_t)(b0 + k) * 256 + t] = acc[k] * acc[k] * 0.25f;
    }

    // Phase 3: prf dots -> g_prf. thread = (r, h, m4), omega amortized over 8 rows
    {
        const int r  = t >> 7;
        const int h  = (t >> 3) & 15;
        const int m4 = t & 7;

        float4 acc[NB];
#pragma unroll
        for (int k = 0; k < NB; k++) acc[k] = make_float4(0.f, 0.f, 0.f, 0.f);

        const float4* og = (const float4*)omega + (size_t)((r * 16 + h) * 64) * 8 + m4;
#pragma unroll 4
        for (int d4 = 0; d4 < 16; d4++) {
            float4 o0 = og[(4 * d4 + 0) * 8];
            float4 o1 = og[(4 * d4 + 1) * 8];
            float4 o2 = og[(4 * d4 + 2) * 8];
            float4 o3 = og[(4 * d4 + 3) * 8];
#pragma unroll
            for (int k = 0; k < NB; k++) {
                float4 xv = ((const float4*)xs[k])[h * 16 + d4];
                acc[k].x += xv.x*o0.x; acc[k].y += xv.x*o0.y; acc[k].z += xv.x*o0.z; acc[k].w += xv.x*o0.w;
                acc[k].x += xv.y*o1.x; acc[k].y += xv.y*o1.y; acc[k].z += xv.y*o1.z; acc[k].w += xv.y*o1.w;
                acc[k].x += xv.z*o2.x; acc[k].y += xv.z*o2.y; acc[k].z += xv.z*o2.z; acc[k].w += xv.z*o2.w;
                acc[k].x += xv.w*o3.x; acc[k].y += xv.w*o3.y; acc[k].z += xv.w*o3.z; acc[k].w += xv.w*o3.w;
            }
        }

        const float sr = r ? s1 : s0;
        const float cr = r ? c1 : c0;
        const float er = r ? e1 : e0;

#pragma unroll
        for (int k = 0; k < NB; k++) {
            float4 a = acc[k];
            float4 pr;
            pr.x = er * __expf(fminf(fmaxf(a.x * cr - sr, -20.f), 20.f));
            pr.y = er * __expf(fminf(fmaxf(a.y * cr - sr, -20.f), 20.f));
            pr.z = er * __expf(fminf(fmaxf(a.z * cr - sr, -20.f), 20.f));
            pr.w = er * __expf(fminf(fmaxf(a.w * cr - sr, -20.f), 20.f));
            // [b][r*512 + h*32 + m4*4]: lanes cover 128 contiguous floats -> coalesced
            *(float4*)&g_prf[(size_t)(b0 + k) * 1024 + r * 512 + h * 32 + m4 * 4] = pr;
        }
    }
}

// Expander: one block per b-row. Stage poly (256 f) + prf (1024 f) in smem,
// then 16 independent contiguous STG.128 per thread (64 KB per block).
__global__ __launch_bounds__(256) void slay_expand(float* __restrict__ out)
{
    __shared__ __align__(16) float pl[256];
    __shared__ __align__(16) float pf[1024];

    const int b = blockIdx.x;
    const int t = threadIdx.x;

    pl[t] = g_poly[(size_t)b * 256 + t];
    ((float4*)pf)[t] = ((const float4*)(g_prf + (size_t)b * 1024))[t];
    __syncthreads();

    float4* ob = (float4*)(out + (size_t)b * 16384);
#pragma unroll
    for (int i = 0; i < 16; i++) {
        const int f  = i * 256 + t;        // float4 index: r*2048 + h*128 + p*8 + m4
        const int m4 = f & 7;
        const int p  = (f >> 3) & 15;
        const int h  = (f >> 7) & 15;
        const int r  = f >> 11;
        const float s = pl[h * 16 + p];
        float4 v = ((const float4*)pf)[r * 128 + h * 8 + m4];
        v.x *= s; v.y *= s; v.z *= s; v.w *= s;
        __stcs(&ob[f], v);
    }
}

extern "C" void kernel_launch(void* const* d_in, const int* in_sizes, int n_in,
                              void* d_out, int out_size) {
    const float* x       = (const float*)d_in[0];
    const float* omega   = (const float*)d_in[1];
    const float* anchors = (const float*)d_in[2];
    float* out = (float*)d_out;

    const double C   = 2.0 + 1e-6;
    const double rt2 = 1.4142135623730951;
    const double n0d = 2.0 - rt2, n1d = 2.0 + rt2;
    const double w0d = (2.0 + rt2) / 4.0, w1d = (2.0 - rt2) / 4.0;

    float s0 = (float)(n0d / C);
    float s1 = (float)(n1d / C);
    float c0 = sqrtf(2.0f * s0);
    float c1 = sqrtf(2.0f * s1);
    float invSqrtM = 1.0f / sqrtf(32.0f);
    float e0 = sqrtf((float)(w0d / C)) * invSqrtM;
    float e1 = sqrtf((float)(w1d / C)) * invSqrtM;

    slay_producer<<<8192 / NB, THREADS>>>(x, omega, anchors, s0, s1, c0, c1, e0, e1);
    slay_expand<<<8192, 256>>>(out);
    (void)in_sizes; (void)n_in; (void)out_size;
}